// round 15
// baseline (speedup 1.0000x reference)
#include <cuda_runtime.h>
#include <cuda_bf16.h>
#include <cstdint>

#define DNF 100000
#define DNA 400
#define DNC 30
#define DNT (DNF + DNA + DNC)
#define DD  256
#define DE  250000
#define DB  3
#define DR  4

// ---------------- device scratch ----------------
__device__ __align__(16) float g_A[(size_t)DNT * DD];
__device__ __align__(16) float g_Bf[(size_t)DNT * DD];
__device__ __align__(16) float g_W[2][DR][DD * DD];
__device__ __align__(16) __nv_bfloat16 g_Wsplit[2][2][DD * DD];
__device__ __align__(16) float g_Y1[DNA * DD];
__device__ __align__(16) float g_Y3[DNC * DD];
__device__ __align__(16) float g_S0[DNA * DD];
__device__ __align__(16) float g_S2[DNC * DD];
__device__ int   g_deg0[DNA];
__device__ int   g_deg1[DNF];
__device__ int   g_deg2[DNC];
__device__ int   g_deg3[DNF];
__device__ float g_inv1[DNF];
__device__ float g_inv3[DNF];
__device__ int   g_off0[DNA], g_cur0[DNA];
__device__ int   g_off2[DNC], g_cur2[DNC];
__device__ int   g_csr0[DE];
__device__ int   g_csr2[DE];

// ---------------- fused setup kernels ----------------
__global__ void zero_deg_all2_kernel(int* deg1, int* deg3, int* deg0, int* deg2) {
    int n = 2 * DNF + DNA + DNC;
    for (int i = blockIdx.x * blockDim.x + threadIdx.x; i < n; i += gridDim.x * blockDim.x) {
        if (i < DNF) deg1[i] = 0;
        else if (i < 2 * DNF) deg3[i - DNF] = 0;
        else if (i < 2 * DNF + DNA) deg0[i - 2 * DNF] = 0;
        else deg2[i - 2 * DNF - DNA] = 0;
    }
}
__global__ void count_flight_kernel(const int* __restrict__ dst1, int* deg1,
                                    const int* __restrict__ dst3, int* deg3) {
    for (int i = blockIdx.x * blockDim.x + threadIdx.x; i < 2 * DE;
         i += gridDim.x * blockDim.x) {
        if (i < DE) atomicAdd(&deg1[dst1[i]], 1);
        else atomicAdd(&deg3[dst3[i - DE]], 1);
    }
}
__global__ void count_small_kernel(const int* __restrict__ dst0, int* deg0,
                                   const int* __restrict__ dst2, int* deg2) {
    __shared__ int h[512];
    int rel = (blockIdx.x < 148) ? 0 : 1;
    int b = (rel == 0) ? blockIdx.x : blockIdx.x - 148;
    const int* dst = rel == 0 ? dst0 : dst2;
    int* deg = rel == 0 ? deg0 : deg2;
    int n = rel == 0 ? DNA : DNC;
    for (int i = threadIdx.x; i < n; i += blockDim.x) h[i] = 0;
    __syncthreads();
    for (int i = b * blockDim.x + threadIdx.x; i < DE; i += 148 * blockDim.x)
        atomicAdd(&h[dst[i]], 1);
    __syncthreads();
    for (int i = threadIdx.x; i < n; i += blockDim.x)
        if (h[i]) atomicAdd(&deg[i], h[i]);
}
__global__ void make_inv_all_kernel(const int* __restrict__ deg1, float* inv1,
                                    const int* __restrict__ deg3, float* inv3) {
    for (int i = blockIdx.x * blockDim.x + threadIdx.x; i < 2 * DNF;
         i += gridDim.x * blockDim.x) {
        if (i < DNF) inv1[i] = 1.0f / (float)max(deg1[i], 1);
        else inv3[i - DNF] = 1.0f / (float)max(deg3[i - DNF], 1);
    }
}
__global__ void scan_small_kernel(const int* __restrict__ deg0, int* off0, int* cur0,
                                  const int* __restrict__ deg2, int* off2, int* cur2) {
    __shared__ int tmp[512];
    const int* deg = blockIdx.x == 0 ? deg0 : deg2;
    int* offs = blockIdx.x == 0 ? off0 : off2;
    int* cur  = blockIdx.x == 0 ? cur0 : cur2;
    int n = blockIdx.x == 0 ? DNA : DNC;
    int t = threadIdx.x;
    int v = (t < n) ? deg[t] : 0;
    tmp[t] = v;
    __syncthreads();
    for (int d = 1; d < 512; d <<= 1) {
        int add = (t >= d) ? tmp[t - d] : 0;
        __syncthreads();
        tmp[t] += add;
        __syncthreads();
    }
    if (t < n) { int e = tmp[t] - v; offs[t] = e; cur[t] = e; }
}
__global__ void fill_csr_both_kernel(const int* __restrict__ src0, const int* __restrict__ dst0,
                                     int* cur0, int* csr0,
                                     const int* __restrict__ src2, const int* __restrict__ dst2,
                                     int* cur2, int* csr2) {
    for (int i = blockIdx.x * blockDim.x + threadIdx.x; i < 2 * DE;
         i += gridDim.x * blockDim.x) {
        if (i < DE) {
            int p = atomicAdd(&cur0[dst0[i]], 1);
            csr0[p] = src0[i];
        } else {
            int j = i - DE;
            int p = atomicAdd(&cur2[dst2[j]], 1);
            csr2[p] = src2[j];
        }
    }
}
__global__ void zero_S_kernel(float* S0, float* S2) {
    int n = (DNA + DNC) * DD;
    for (int i = blockIdx.x * blockDim.x + threadIdx.x; i < n; i += gridDim.x * blockDim.x) {
        if (i < DNA * DD) S0[i] = 0.0f;
        else S2[i - DNA * DD] = 0.0f;
    }
}

// ---------------- weight prep ----------------
__global__ void compute_W_all_kernel(const float* __restrict__ basis0,
                                     const float* __restrict__ comp0, float* W0,
                                     const float* __restrict__ basis1,
                                     const float* __restrict__ comp1, float* W1) {
    int total = DR * DD * DD;
    for (int idx = blockIdx.x * blockDim.x + threadIdx.x; idx < 2 * total;
         idx += gridDim.x * blockDim.x) {
        int layer = idx / total;
        int rem = idx % total;
        int r = rem / (DD * DD), io = rem % (DD * DD);
        const float* basis = layer == 0 ? basis0 : basis1;
        const float* comp  = layer == 0 ? comp0 : comp1;
        float acc = 0.0f;
#pragma unroll
        for (int b = 0; b < DB; b++)
            acc += comp[r * DB + b] * basis[(size_t)b * DD * DD + io];
        (layer == 0 ? W0 : W1)[rem] = acc;
    }
}
__global__ void prep_wsplit_kernel(const float* __restrict__ W,
                                   __nv_bfloat16* __restrict__ Wh,
                                   __nv_bfloat16* __restrict__ Wl) {
    int idx = blockIdx.x * blockDim.x + threadIdx.x;
    if (idx >= DD * DD) return;
    int n = idx >> 8, k = idx & 255;
    float v = W[k * 256 + n];
    __nv_bfloat16 hi = __float2bfloat16(v);
    __nv_bfloat16 lo = __float2bfloat16(v - __bfloat162float(hi));
    Wh[n * 256 + k] = hi;
    Wl[n * 256 + k] = lo;
}

// ---------------- fused encoder ----------------
#define ENC_FBLOCKS 296
__global__ void encode_all_kernel(const float* __restrict__ Xf, const float* __restrict__ Wf,
                                  const float* __restrict__ bf,
                                  const float* __restrict__ Xa, const float* __restrict__ Wa,
                                  const float* __restrict__ ba,
                                  const float* __restrict__ Xc, const float* __restrict__ Wc,
                                  const float* __restrict__ bc,
                                  float* __restrict__ out) {
    int tid = threadIdx.x;
    if (blockIdx.x < ENC_FBLOCKS) {
        __shared__ float Ws[32 * DD];
        __shared__ float Xs[32 * 32];
        for (int i = tid; i < 32 * DD; i += 256) Ws[i] = Wf[i];
        int col = tid;
        float bv = bf[col];
        const int NT = (DNF + 31) / 32;
        for (int tile = blockIdx.x; tile < NT; tile += ENC_FBLOCKS) {
            __syncthreads();
            int r0 = tile * 32;
            int rows = min(32, DNF - r0);
            for (int i = tid; i < rows * 32; i += 256) Xs[i] = Xf[(size_t)r0 * 32 + i];
            __syncthreads();
            for (int row = 0; row < rows; row++) {
                float acc = 0.0f;
#pragma unroll
                for (int k = 0; k < 32; k++) acc += Xs[row * 32 + k] * Ws[k * DD + col];
                out[(size_t)(r0 + row) * DD + col] = fmaxf(acc + bv, 0.0f);
            }
        }
    } else {
        int r = blockIdx.x - ENC_FBLOCKS;
        int w = tid >> 5, lane = tid & 31;
        int col = w * 32 + lane;
        if (r < DNA) {
            const float* x = Xa + (size_t)r * 16;
            float acc = 0.0f;
#pragma unroll
            for (int k = 0; k < 16; k++) acc += x[k] * Wa[k * 256 + col];
            out[(size_t)(DNF + r) * DD + col] = fmaxf(acc + ba[col], 0.0f);
        } else {
            int rc = r - DNA;
            const float* x = Xc + (size_t)rc * 8;
            float acc = 0.0f;
#pragma unroll
            for (int k = 0; k < 8; k++) acc += x[k] * Wc[k * 256 + col];
            out[(size_t)(DNF + DNA + rc) * DD + col] = fmaxf(acc + bc[col], 0.0f);
        }
    }
}

// ---------------- fused small-M matmuls ----------------
__global__ void yms_kernel(const float* __restrict__ Aair, const float* __restrict__ Acar,
                           const float* __restrict__ Wr1, const float* __restrict__ Wr3,
                           float* __restrict__ Y1, float* __restrict__ Y3, int reluIn) {
    int b = blockIdx.x;
    int w = threadIdx.x >> 5, lane = threadIdx.x & 31;
    int col = w * 32 + lane;
    const float* a;
    const float* W;
    float* C;
    if (b < DNA) { a = Aair + (size_t)b * 256; W = Wr1; C = Y1 + (size_t)b * 256; }
    else { int rc = b - DNA; a = Acar + (size_t)rc * 256; W = Wr3; C = Y3 + (size_t)rc * 256; }
    float acc = 0.0f;
#pragma unroll 4
    for (int k = 0; k < 256; k += 4) {
        float4 av = *(const float4*)(a + k);
        if (reluIn) {
            av.x = fmaxf(av.x, 0.f); av.y = fmaxf(av.y, 0.f);
            av.z = fmaxf(av.z, 0.f); av.w = fmaxf(av.w, 0.f);
        }
        acc += av.x * W[(k + 0) * 256 + col] + av.y * W[(k + 1) * 256 + col] +
               av.z * W[(k + 2) * 256 + col] + av.w * W[(k + 3) * 256 + col];
    }
    C[col] = acc;
}
__global__ void sms_kernel(const float* __restrict__ S0, const float* __restrict__ S2,
                           const float* __restrict__ Wr0, const float* __restrict__ Wr2,
                           float* __restrict__ Bf) {
    int b = blockIdx.x;
    int w = threadIdx.x >> 5, lane = threadIdx.x & 31;
    int col = w * 32 + lane;
    const float* a;
    const float* W;
    float* C;
    if (b < DNA) { a = S0 + (size_t)b * 256; W = Wr0; C = Bf + (size_t)(DNF + b) * 256; }
    else {
        int rc = b - DNA;
        a = S2 + (size_t)rc * 256; W = Wr2; C = Bf + (size_t)(DNF + DNA + rc) * 256;
    }
    float acc = 0.0f;
#pragma unroll 4
    for (int k = 0; k < 256; k += 4) {
        float4 av = *(const float4*)(a + k);
        acc += av.x * W[(k + 0) * 256 + col] + av.y * W[(k + 1) * 256 + col] +
               av.z * W[(k + 2) * 256 + col] + av.w * W[(k + 3) * 256 + col];
    }
    C[col] += acc;
}

// ---------------- fused CSR gather (rel0 + rel2) ----------------
__global__ void gather_both_kernel(const float* __restrict__ tab,
                                   const int* __restrict__ csr0, const int* __restrict__ off0,
                                   const int* __restrict__ deg0, float* __restrict__ S0,
                                   const int* __restrict__ csr2, const int* __restrict__ off2,
                                   const int* __restrict__ deg2, float* __restrict__ S2) {
    int w = (blockIdx.x * blockDim.x + threadIdx.x) >> 5;
    int lane = threadIdx.x & 31;
    const int N0 = DNA * 8 * 8;
    const int N2 = DNC * 8 * 64;
    if (w >= N0 + N2) return;
    const int* csr;
    const int* offs;
    const int* deg;
    float* S;
    int row, cg, chunk, split;
    if (w < N0) {
        split = 8;
        row = w / 64; int rr = w % 64; cg = rr & 7; chunk = rr >> 3;
        csr = csr0; offs = off0; deg = deg0; S = S0;
    } else {
        int w2 = w - N0;
        split = 64;
        row = w2 / 512; int rr = w2 % 512; cg = rr & 7; chunk = rr >> 3;
        csr = csr2; offs = off2; deg = deg2; S = S2;
    }
    int col = cg * 32 + lane;
    int d = deg[row], beg = offs[row];
    int per = (d + split - 1) / split;
    int s0 = beg + chunk * per;
    int s1 = min(beg + d, s0 + per);
    if (s0 >= s1) return;
    float acc = 0.0f;
    int e = s0;
    for (; e + 4 <= s1; e += 4) {
        int i0 = csr[e], i1 = csr[e + 1], i2 = csr[e + 2], i3 = csr[e + 3];
        acc += (tab[(size_t)i0 * DD + col] + tab[(size_t)i1 * DD + col]) +
               (tab[(size_t)i2 * DD + col] + tab[(size_t)i3 * DD + col]);
    }
    for (; e < s1; e++) acc += tab[(size_t)csr[e] * DD + col];
    acc *= 1.0f / (float)max(d, 1);
    atomicAdd(&S[(size_t)row * DD + col], acc);
}

// ---------------- resident-smem bf16 split GEMM (pair-permuted u64 frags) ----------------
__device__ __forceinline__ uint32_t pack_bf16_hi(float f0, float f1) {
    return (uint32_t)__bfloat16_as_ushort(__float2bfloat16(f0)) |
           ((uint32_t)__bfloat16_as_ushort(__float2bfloat16(f1)) << 16);
}
__device__ __forceinline__ uint32_t pack_bf16_lo(float f0, float f1) {
    __nv_bfloat16 h0 = __float2bfloat16(f0);
    __nv_bfloat16 h1 = __float2bfloat16(f1);
    __nv_bfloat16 l0 = __float2bfloat16(f0 - __bfloat162float(h0));
    __nv_bfloat16 l1 = __float2bfloat16(f1 - __bfloat162float(h1));
    return (uint32_t)__bfloat16_as_ushort(l0) |
           ((uint32_t)__bfloat16_as_ushort(l1) << 16);
}
__device__ __forceinline__ void mma16816(float* c, const uint32_t* a,
                                         const uint32_t* b) {
    asm volatile(
        "mma.sync.aligned.m16n8k16.row.col.f32.bf16.bf16.f32 "
        "{%0,%1,%2,%3}, {%4,%5,%6,%7}, {%8,%9}, {%0,%1,%2,%3};"
        : "+f"(c[0]), "+f"(c[1]), "+f"(c[2]), "+f"(c[3])
        : "r"(a[0]), "r"(a[1]), "r"(a[2]), "r"(a[3]), "r"(b[0]), "r"(b[1]));
}
// slot permutation: pair p (0..15) -> slot; thread t reads slots {2t, 2t+1} =
// pairs {t, t+4} of its ks-half as one aligned u64.
__device__ __forceinline__ int pos16(int p) {
    return ((p >> 3) << 3) + ((p & 3) << 1) + ((p >> 2) & 1);
}

#define SPAD 18
#define CHUNK (128 * SPAD)
#define MM_DSMEM (3 * 8 * CHUNK * 4)

__global__ void __launch_bounds__(256)
mma_resident_kernel(const float* __restrict__ A,
                    const uint32_t* __restrict__ WhU,
                    const uint32_t* __restrict__ WlU,
                    const float* __restrict__ bias, float* __restrict__ C,
                    int M, int reluA) {
    extern __shared__ uint32_t dsm[];
    uint32_t* sAh = dsm;
    uint32_t* sAl = dsm + 8 * CHUNK;
    uint32_t* sB  = dsm + 16 * CHUNK;

    int tid = threadIdx.x;
    int lane = tid & 31, wid = tid >> 5;
    int warpM = wid >> 2;
    int warpN = wid & 3;
    int m0 = blockIdx.x * 128;
    int n0 = blockIdx.y * 128;

    float acc[4][4][4];
#pragma unroll
    for (int i = 0; i < 4; i++)
#pragma unroll
        for (int j = 0; j < 4; j++)
#pragma unroll
            for (int q = 0; q < 4; q++) acc[i][j][q] = 0.0f;

    // ---- load + split-convert A (once), chunk-major, pair-permuted slots ----
#pragma unroll 2
    for (int c = 0; c < 8; c++) {
#pragma unroll
        for (int j = 0; j < 4; j++) {
            int id = j * 256 + tid;
            int row = id >> 3, q = id & 7;
            int rg = m0 + row;
            float4 v = make_float4(0.f, 0.f, 0.f, 0.f);
            if (rg < M) v = *(const float4*)(A + (size_t)rg * 256 + c * 32 + q * 4);
            if (reluA) {
                v.x = fmaxf(v.x, 0.f); v.y = fmaxf(v.y, 0.f);
                v.z = fmaxf(v.z, 0.f); v.w = fmaxf(v.w, 0.f);
            }
            int rbse = c * CHUNK + row * SPAD;
            int s0 = rbse + pos16(2 * q);
            int s1 = rbse + pos16(2 * q + 1);
            sAh[s0] = pack_bf16_hi(v.x, v.y);
            sAh[s1] = pack_bf16_hi(v.z, v.w);
            sAl[s0] = pack_bf16_lo(v.x, v.y);
            sAl[s1] = pack_bf16_lo(v.z, v.w);
        }
    }
    // ---- load Bh (pair-permuted slots) ----
#pragma unroll 2
    for (int c = 0; c < 8; c++) {
#pragma unroll
        for (int j = 0; j < 8; j++) {
            int id = j * 256 + tid;
            int n = id >> 4, cc = id & 15;
            sB[c * CHUNK + n * SPAD + pos16(cc)] = WhU[(size_t)(n0 + n) * 128 + c * 16 + cc];
        }
    }
    __syncthreads();

    int rbase = warpM * 64 + (lane >> 2);
    int nbase = warpN * 32 + (lane >> 2);
    int tq = lane & 3;

    auto mmaAll = [&](const uint32_t* aB) {
#pragma unroll 2
        for (int c = 0; c < 8; c++) {
            const uint32_t* ac = aB + c * CHUNK;
            const uint32_t* bc = sB + c * CHUNK;
#pragma unroll
            for (int ks = 0; ks < 2; ks++) {
                int so = ks * 8 + tq * 2;
                uint32_t af[4][4];
                uint32_t bfr[4][2];
#pragma unroll
                for (int mt = 0; mt < 4; mt++) {
                    int r = rbase + mt * 16;
                    unsigned long long lo =
                        *(const unsigned long long*)(ac + r * SPAD + so);
                    unsigned long long hi =
                        *(const unsigned long long*)(ac + (r + 8) * SPAD + so);
                    af[mt][0] = (uint32_t)lo; af[mt][2] = (uint32_t)(lo >> 32);
                    af[mt][1] = (uint32_t)hi; af[mt][3] = (uint32_t)(hi >> 32);
                }
#pragma unroll
                for (int nt = 0; nt < 4; nt++) {
                    int n = nbase + nt * 8;
                    unsigned long long v =
                        *(const unsigned long long*)(bc + n * SPAD + so);
                    bfr[nt][0] = (uint32_t)v; bfr[nt][1] = (uint32_t)(v >> 32);
                }
#pragma unroll
                for (int mt = 0; mt < 4; mt++)
#pragma unroll
                    for (int nt = 0; nt < 4; nt++)
                        mma16816(acc[mt][nt], af[mt], bfr[nt]);
            }
        }
    };

    mmaAll(sAh);    // Ah @ Wh
    mmaAll(sAl);    // Al @ Wh
    __syncthreads();

    // ---- overwrite B with Bl ----
#pragma unroll 2
    for (int c = 0; c < 8; c++) {
#pragma unroll
        for (int j = 0; j < 8; j++) {
            int id = j * 256 + tid;
            int n = id >> 4, cc = id & 15;
            sB[c * CHUNK + n * SPAD + pos16(cc)] = WlU[(size_t)(n0 + n) * 128 + c * 16 + cc];
        }
    }
    __syncthreads();

    mmaAll(sAh);    // Ah @ Wl

    // ---- epilogue ----
#pragma unroll
    for (int mt = 0; mt < 4; mt++) {
        int r = m0 + warpM * 64 + mt * 16 + (lane >> 2);
#pragma unroll
        for (int nt = 0; nt < 4; nt++) {
            int c = n0 + warpN * 32 + nt * 8 + (lane & 3) * 2;
            float b0 = bias[c], b1 = bias[c + 1];
            if (r < M) {
                float2 v0 = make_float2(acc[mt][nt][0] + b0, acc[mt][nt][1] + b1);
                *(float2*)(C + (size_t)r * 256 + c) = v0;
            }
            if (r + 8 < M) {
                float2 v1 = make_float2(acc[mt][nt][2] + b0, acc[mt][nt][3] + b1);
                *(float2*)(C + (size_t)(r + 8) * 256 + c) = v1;
            }
        }
    }
}

// ---------------- fused scatter (rel1 + rel3) ----------------
__device__ __forceinline__ void red_add_v4(float* addr, float4 v) {
    asm volatile("red.global.add.v4.f32 [%0], {%1,%2,%3,%4};"
                 :: "l"(addr), "f"(v.x), "f"(v.y), "f"(v.z), "f"(v.w) : "memory");
}
__global__ void scatter_both_kernel(const float* __restrict__ Y1,
                                    const int* __restrict__ src1, const int* __restrict__ dst1,
                                    const float* __restrict__ inv1,
                                    const float* __restrict__ Y3,
                                    const int* __restrict__ src3, const int* __restrict__ dst3,
                                    const float* __restrict__ inv3,
                                    float* __restrict__ out) {
    int w = (blockIdx.x * blockDim.x + threadIdx.x) >> 5;
    int lane = threadIdx.x & 31;
    if (w >= 2 * DE) return;
    const float* tab;
    int s, d;
    float sc;
    if (w < DE) {
        s = src1[w]; d = dst1[w]; sc = inv1[d]; tab = Y1;
    } else {
        int e = w - DE;
        s = src3[e]; d = dst3[e]; sc = inv3[d]; tab = Y3;
    }
    const float4* in4 = (const float4*)(tab + (size_t)s * DD);
    float4 a = in4[lane], b = in4[lane + 32];
    a.x *= sc; a.y *= sc; a.z *= sc; a.w *= sc;
    b.x *= sc; b.y *= sc; b.z *= sc; b.w *= sc;
    float* ob = out + (size_t)d * DD;
    red_add_v4(ob + lane * 4, a);
    red_add_v4(ob + (lane + 32) * 4, b);
}

// readout
__global__ void readout_kernel(const float* __restrict__ X, const float* __restrict__ Wout,
                               const float* __restrict__ bout, float* __restrict__ out,
                               int M) {
    int w = (blockIdx.x * blockDim.x + threadIdx.x) >> 5;
    int lane = threadIdx.x & 31;
    if (w >= M) return;
    const float4* x4 = (const float4*)(X + (size_t)w * DD);
    const float4* w4 = (const float4*)Wout;
    float4 a = x4[lane], wa = w4[lane];
    float4 b = x4[lane + 32], wb = w4[lane + 32];
    float s = fmaxf(a.x, 0.f) * wa.x + fmaxf(a.y, 0.f) * wa.y +
              fmaxf(a.z, 0.f) * wa.z + fmaxf(a.w, 0.f) * wa.w +
              fmaxf(b.x, 0.f) * wb.x + fmaxf(b.y, 0.f) * wb.y +
              fmaxf(b.z, 0.f) * wb.z + fmaxf(b.w, 0.f) * wb.w;
#pragma unroll
    for (int off = 16; off > 0; off >>= 1) s += __shfl_down_sync(0xffffffffu, s, off);
    if (lane == 0) out[w] = s + bout[0];
}

// ---------------- launch ----------------
extern "C" void kernel_launch(void* const* d_in, const int* in_sizes, int n_in,
                              void* d_out, int out_size) {
    (void)in_sizes; (void)n_in; (void)out_size;
    const float* x_flight  = (const float*)d_in[0];
    const float* x_airport = (const float*)d_in[1];
    const float* x_carrier = (const float*)d_in[2];
    const float* W_f = (const float*)d_in[3];
    const float* b_f = (const float*)d_in[4];
    const float* W_a = (const float*)d_in[5];
    const float* b_a = (const float*)d_in[6];
    const float* W_c = (const float*)d_in[7];
    const float* b_c = (const float*)d_in[8];
    const float* basis0 = (const float*)d_in[9];
    const float* comp0  = (const float*)d_in[10];
    const float* root0  = (const float*)d_in[11];
    const float* bias0  = (const float*)d_in[12];
    const float* basis1 = (const float*)d_in[13];
    const float* comp1  = (const float*)d_in[14];
    const float* root1  = (const float*)d_in[15];
    const float* bias1  = (const float*)d_in[16];
    const float* W_out  = (const float*)d_in[17];
    const float* b_out  = (const float*)d_in[18];
    const int* src0 = (const int*)d_in[19];
    const int* dst0 = (const int*)d_in[20];
    const int* src1 = (const int*)d_in[21];
    const int* dst1 = (const int*)d_in[22];
    const int* src2 = (const int*)d_in[23];
    const int* dst2 = (const int*)d_in[24];
    const int* src3 = (const int*)d_in[25];
    const int* dst3 = (const int*)d_in[26];
    float* out_final = (float*)d_out;

    void *pA, *pB, *pW, *pWs, *pY1, *pY3, *pS0, *pS2;
    void *pd0, *pd1, *pd2, *pd3, *pi1, *pi3;
    void *po0, *pc0, *po2, *pc2, *pe0, *pe2;
    cudaGetSymbolAddress(&pA, g_A);       cudaGetSymbolAddress(&pB, g_Bf);
    cudaGetSymbolAddress(&pW, g_W);       cudaGetSymbolAddress(&pWs, g_Wsplit);
    cudaGetSymbolAddress(&pY1, g_Y1);     cudaGetSymbolAddress(&pY3, g_Y3);
    cudaGetSymbolAddress(&pS0, g_S0);     cudaGetSymbolAddress(&pS2, g_S2);
    cudaGetSymbolAddress(&pd0, g_deg0);   cudaGetSymbolAddress(&pd1, g_deg1);
    cudaGetSymbolAddress(&pd2, g_deg2);   cudaGetSymbolAddress(&pd3, g_deg3);
    cudaGetSymbolAddress(&pi1, g_inv1);   cudaGetSymbolAddress(&pi3, g_inv3);
    cudaGetSymbolAddress(&po0, g_off0);   cudaGetSymbolAddress(&pc0, g_cur0);
    cudaGetSymbolAddress(&po2, g_off2);   cudaGetSymbolAddress(&pc2, g_cur2);
    cudaGetSymbolAddress(&pe0, g_csr0);   cudaGetSymbolAddress(&pe2, g_csr2);

    float* A = (float*)pA;  float* Bf = (float*)pB;  float* W = (float*)pW;
    __nv_bfloat16* Ws = (__nv_bfloat16*)pWs;
    float* Y1 = (float*)pY1; float* Y3 = (float*)pY3;
    float* S0 = (float*)pS0; float* S2 = (float*)pS2;
    int* deg0 = (int*)pd0; int* deg1 = (int*)pd1;
    int* deg2 = (int*)pd2; int* deg3 = (int*)pd3;
    float* inv1 = (float*)pi1; float* inv3 = (float*)pi3;
    int* off0 = (int*)po0; int* cur0 = (int*)pc0;
    int* off2 = (int*)po2; int* cur2 = (int*)pc2;
    int* csr0 = (int*)pe0; int* csr2 = (int*)pe2;

    const size_t WSZ = (size_t)DD * DD;
    float* W0 = W;
    float* W1 = W + DR * WSZ;
    __nv_bfloat16* Wh0 = Ws;
    __nv_bfloat16* Wl0 = Ws + WSZ;
    __nv_bfloat16* Wh1 = Ws + 2 * WSZ;
    __nv_bfloat16* Wl1 = Ws + 3 * WSZ;

    cudaFuncSetAttribute(mma_resident_kernel,
                         cudaFuncAttributeMaxDynamicSharedMemorySize, MM_DSMEM);

    dim3 gFull((DNT + 127) / 128, 2);
    dim3 gNF((DNF + 127) / 128, 2);
    const int scatter2Blocks = (2 * DE * 32 + 255) / 256;
    const int gatherBlocks = ((DNA * 64 + DNC * 512) * 32 + 255) / 256;

    // 0: deg zero
    zero_deg_all2_kernel<<<784, 256>>>(deg1, deg3, deg0, deg2);
    // 1: split root0
    prep_wsplit_kernel<<<(DD * DD + 255) / 256, 256>>>(root0, Wh0, Wl0);
    // 2: all encoders fused -> A
    encode_all_kernel<<<ENC_FBLOCKS + DNA + DNC, 256>>>(
        x_flight, W_f, b_f, x_airport, W_a, b_a, x_carrier, W_c, b_c, A);
    // 3: layer-0 root GEMM (ncu capture target)
    mma_resident_kernel<<<gFull, 256, MM_DSMEM>>>(
        A, (const uint32_t*)Wh0, (const uint32_t*)Wl0, bias0, Bf, DNT, 0);
    // 4-5: degree counts
    count_flight_kernel<<<1954, 256>>>(dst1, deg1, dst3, deg3);
    count_small_kernel<<<296, 256>>>(dst0, deg0, dst2, deg2);
    // 6: split root1
    prep_wsplit_kernel<<<(DD * DD + 255) / 256, 256>>>(root1, Wh1, Wl1);
    // 7: relation weights both layers
    compute_W_all_kernel<<<2048, 256>>>(basis0, comp0, W0, basis1, comp1, W1);
    // 8-10: inv, scans, CSR fill
    make_inv_all_kernel<<<782, 256>>>(deg1, inv1, deg3, inv3);
    scan_small_kernel<<<2, 512>>>(deg0, off0, cur0, deg2, off2, cur2);
    fill_csr_both_kernel<<<1954, 256>>>(src0, dst0, cur0, csr0, src2, dst2, cur2, csr2);
    // 11: layer-0 relation messages
    yms_kernel<<<DNA + DNC, 256>>>(A + (size_t)DNF * DD, A + (size_t)(DNF + DNA) * DD,
                                   W0 + 1 * WSZ, W0 + 3 * WSZ, Y1, Y3, 0);
    // 12-14: rel0/rel2 aggregates
    zero_S_kernel<<<430, 256>>>(S0, S2);
    gather_both_kernel<<<gatherBlocks, 256>>>(A, csr0, off0, deg0, S0,
                                              csr2, off2, deg2, S2);
    sms_kernel<<<DNA + DNC, 256>>>(S0, S2, W0 + 0 * WSZ, W0 + 2 * WSZ, Bf);
    // 15: fused scatter layer 0
    scatter_both_kernel<<<scatter2Blocks, 256>>>(Y1, src1, dst1, inv1,
                                                 Y3, src3, dst3, inv3, Bf);
    // 16: layer-1 root GEMM
    mma_resident_kernel<<<gNF, 256, MM_DSMEM>>>(
        Bf, (const uint32_t*)Wh1, (const uint32_t*)Wl1, bias1, A, DNF, 1);
    // 17: layer-1 relation messages
    yms_kernel<<<DNA + DNC, 256>>>(Bf + (size_t)DNF * DD, Bf + (size_t)(DNF + DNA) * DD,
                                   W1 + 1 * WSZ, W1 + 3 * WSZ, Y1, Y3, 1);
    // 18: fused scatter layer 1
    scatter_both_kernel<<<scatter2Blocks, 256>>>(Y1, src1, dst1, inv1,
                                                 Y3, src3, dst3, inv3, A);
    // 19: readout
    readout_kernel<<<(DNF * 32 + 255) / 256, 256>>>(A, W_out, b_out, out_final, DNF);
}

// round 17
// speedup vs baseline: 1.0297x; 1.0297x over previous
#include <cuda_runtime.h>
#include <cuda_bf16.h>
#include <cstdint>

#define DNF 100000
#define DNA 400
#define DNC 30
#define DNT (DNF + DNA + DNC)
#define DD  256
#define DE  250000
#define DB  3
#define DR  4

// ---------------- device scratch ----------------
__device__ __align__(16) float g_A[(size_t)DNT * DD];
__device__ __align__(16) float g_Bf[(size_t)DNT * DD];
__device__ __align__(16) float g_W[2][DR][DD * DD];
__device__ __align__(16) __nv_bfloat16 g_Wsplit[2][2][DD * DD];
__device__ __align__(16) float g_Y1[DNA * DD];
__device__ __align__(16) float g_Y3[DNC * DD];
__device__ __align__(16) float g_S0[DNA * DD];
__device__ __align__(16) float g_S2[DNC * DD];
__device__ int   g_deg0[DNA];
__device__ int   g_deg1[DNF];
__device__ int   g_deg2[DNC];
__device__ int   g_deg3[DNF];
__device__ float g_inv1[DNF];
__device__ float g_inv3[DNF];
__device__ int   g_off0[DNA], g_cur0[DNA];
__device__ int   g_off2[DNC], g_cur2[DNC];
__device__ int   g_csr0[DE];
__device__ int   g_csr2[DE];

// ---------------- fused setup kernels ----------------
__global__ void zero_deg_all2_kernel(int* deg1, int* deg3, int* deg0, int* deg2) {
    int n = 2 * DNF + DNA + DNC;
    for (int i = blockIdx.x * blockDim.x + threadIdx.x; i < n; i += gridDim.x * blockDim.x) {
        if (i < DNF) deg1[i] = 0;
        else if (i < 2 * DNF) deg3[i - DNF] = 0;
        else if (i < 2 * DNF + DNA) deg0[i - 2 * DNF] = 0;
        else deg2[i - 2 * DNF - DNA] = 0;
    }
}
__global__ void count_flight_kernel(const int* __restrict__ dst1, int* deg1,
                                    const int* __restrict__ dst3, int* deg3) {
    for (int i = blockIdx.x * blockDim.x + threadIdx.x; i < 2 * DE;
         i += gridDim.x * blockDim.x) {
        if (i < DE) atomicAdd(&deg1[dst1[i]], 1);
        else atomicAdd(&deg3[dst3[i - DE]], 1);
    }
}
__global__ void count_small_kernel(const int* __restrict__ dst0, int* deg0,
                                   const int* __restrict__ dst2, int* deg2) {
    __shared__ int h[512];
    int rel = (blockIdx.x < 148) ? 0 : 1;
    int b = (rel == 0) ? blockIdx.x : blockIdx.x - 148;
    const int* dst = rel == 0 ? dst0 : dst2;
    int* deg = rel == 0 ? deg0 : deg2;
    int n = rel == 0 ? DNA : DNC;
    for (int i = threadIdx.x; i < n; i += blockDim.x) h[i] = 0;
    __syncthreads();
    for (int i = b * blockDim.x + threadIdx.x; i < DE; i += 148 * blockDim.x)
        atomicAdd(&h[dst[i]], 1);
    __syncthreads();
    for (int i = threadIdx.x; i < n; i += blockDim.x)
        if (h[i]) atomicAdd(&deg[i], h[i]);
}
__global__ void make_inv_all_kernel(const int* __restrict__ deg1, float* inv1,
                                    const int* __restrict__ deg3, float* inv3) {
    for (int i = blockIdx.x * blockDim.x + threadIdx.x; i < 2 * DNF;
         i += gridDim.x * blockDim.x) {
        if (i < DNF) inv1[i] = 1.0f / (float)max(deg1[i], 1);
        else inv3[i - DNF] = 1.0f / (float)max(deg3[i - DNF], 1);
    }
}
__global__ void scan_small_kernel(const int* __restrict__ deg0, int* off0, int* cur0,
                                  const int* __restrict__ deg2, int* off2, int* cur2) {
    __shared__ int tmp[512];
    const int* deg = blockIdx.x == 0 ? deg0 : deg2;
    int* offs = blockIdx.x == 0 ? off0 : off2;
    int* cur  = blockIdx.x == 0 ? cur0 : cur2;
    int n = blockIdx.x == 0 ? DNA : DNC;
    int t = threadIdx.x;
    int v = (t < n) ? deg[t] : 0;
    tmp[t] = v;
    __syncthreads();
    for (int d = 1; d < 512; d <<= 1) {
        int add = (t >= d) ? tmp[t - d] : 0;
        __syncthreads();
        tmp[t] += add;
        __syncthreads();
    }
    if (t < n) { int e = tmp[t] - v; offs[t] = e; cur[t] = e; }
}
__global__ void fill_csr_both_kernel(const int* __restrict__ src0, const int* __restrict__ dst0,
                                     int* cur0, int* csr0,
                                     const int* __restrict__ src2, const int* __restrict__ dst2,
                                     int* cur2, int* csr2) {
    for (int i = blockIdx.x * blockDim.x + threadIdx.x; i < 2 * DE;
         i += gridDim.x * blockDim.x) {
        if (i < DE) {
            int p = atomicAdd(&cur0[dst0[i]], 1);
            csr0[p] = src0[i];
        } else {
            int j = i - DE;
            int p = atomicAdd(&cur2[dst2[j]], 1);
            csr2[p] = src2[j];
        }
    }
}
__global__ void zero_S_kernel(float* S0, float* S2) {
    int n = (DNA + DNC) * DD;
    for (int i = blockIdx.x * blockDim.x + threadIdx.x; i < n; i += gridDim.x * blockDim.x) {
        if (i < DNA * DD) S0[i] = 0.0f;
        else S2[i - DNA * DD] = 0.0f;
    }
}

// ---------------- weight prep ----------------
__global__ void compute_W_all_kernel(const float* __restrict__ basis0,
                                     const float* __restrict__ comp0, float* W0,
                                     const float* __restrict__ basis1,
                                     const float* __restrict__ comp1, float* W1) {
    int total = DR * DD * DD;
    for (int idx = blockIdx.x * blockDim.x + threadIdx.x; idx < 2 * total;
         idx += gridDim.x * blockDim.x) {
        int layer = idx / total;
        int rem = idx % total;
        int r = rem / (DD * DD), io = rem % (DD * DD);
        const float* basis = layer == 0 ? basis0 : basis1;
        const float* comp  = layer == 0 ? comp0 : comp1;
        float acc = 0.0f;
#pragma unroll
        for (int b = 0; b < DB; b++)
            acc += comp[r * DB + b] * basis[(size_t)b * DD * DD + io];
        (layer == 0 ? W0 : W1)[rem] = acc;
    }
}
__global__ void prep_wsplit_kernel(const float* __restrict__ W,
                                   __nv_bfloat16* __restrict__ Wh,
                                   __nv_bfloat16* __restrict__ Wl) {
    int idx = blockIdx.x * blockDim.x + threadIdx.x;
    if (idx >= DD * DD) return;
    int n = idx >> 8, k = idx & 255;
    float v = W[k * 256 + n];
    __nv_bfloat16 hi = __float2bfloat16(v);
    __nv_bfloat16 lo = __float2bfloat16(v - __bfloat162float(hi));
    Wh[n * 256 + k] = hi;
    Wl[n * 256 + k] = lo;
}

// ---------------- fused encoder ----------------
#define ENC_FBLOCKS 296
__global__ void encode_all_kernel(const float* __restrict__ Xf, const float* __restrict__ Wf,
                                  const float* __restrict__ bf,
                                  const float* __restrict__ Xa, const float* __restrict__ Wa,
                                  const float* __restrict__ ba,
                                  const float* __restrict__ Xc, const float* __restrict__ Wc,
                                  const float* __restrict__ bc,
                                  float* __restrict__ out) {
    int tid = threadIdx.x;
    if (blockIdx.x < ENC_FBLOCKS) {
        __shared__ float Ws[32 * DD];
        __shared__ float Xs[32 * 32];
        for (int i = tid; i < 32 * DD; i += 256) Ws[i] = Wf[i];
        int col = tid;
        float bv = bf[col];
        const int NT = (DNF + 31) / 32;
        for (int tile = blockIdx.x; tile < NT; tile += ENC_FBLOCKS) {
            __syncthreads();
            int r0 = tile * 32;
            int rows = min(32, DNF - r0);
            for (int i = tid; i < rows * 32; i += 256) Xs[i] = Xf[(size_t)r0 * 32 + i];
            __syncthreads();
            for (int row = 0; row < rows; row++) {
                float acc = 0.0f;
#pragma unroll
                for (int k = 0; k < 32; k++) acc += Xs[row * 32 + k] * Ws[k * DD + col];
                out[(size_t)(r0 + row) * DD + col] = fmaxf(acc + bv, 0.0f);
            }
        }
    } else {
        int r = blockIdx.x - ENC_FBLOCKS;
        int w = tid >> 5, lane = tid & 31;
        int col = w * 32 + lane;
        if (r < DNA) {
            const float* x = Xa + (size_t)r * 16;
            float acc = 0.0f;
#pragma unroll
            for (int k = 0; k < 16; k++) acc += x[k] * Wa[k * 256 + col];
            out[(size_t)(DNF + r) * DD + col] = fmaxf(acc + ba[col], 0.0f);
        } else {
            int rc = r - DNA;
            const float* x = Xc + (size_t)rc * 8;
            float acc = 0.0f;
#pragma unroll
            for (int k = 0; k < 8; k++) acc += x[k] * Wc[k * 256 + col];
            out[(size_t)(DNF + DNA + rc) * DD + col] = fmaxf(acc + bc[col], 0.0f);
        }
    }
}

// ---------------- fused small-M matmuls ----------------
__global__ void yms_kernel(const float* __restrict__ Aair, const float* __restrict__ Acar,
                           const float* __restrict__ Wr1, const float* __restrict__ Wr3,
                           float* __restrict__ Y1, float* __restrict__ Y3, int reluIn) {
    int b = blockIdx.x;
    int w = threadIdx.x >> 5, lane = threadIdx.x & 31;
    int col = w * 32 + lane;
    const float* a;
    const float* W;
    float* C;
    if (b < DNA) { a = Aair + (size_t)b * 256; W = Wr1; C = Y1 + (size_t)b * 256; }
    else { int rc = b - DNA; a = Acar + (size_t)rc * 256; W = Wr3; C = Y3 + (size_t)rc * 256; }
    float acc = 0.0f;
#pragma unroll 4
    for (int k = 0; k < 256; k += 4) {
        float4 av = *(const float4*)(a + k);
        if (reluIn) {
            av.x = fmaxf(av.x, 0.f); av.y = fmaxf(av.y, 0.f);
            av.z = fmaxf(av.z, 0.f); av.w = fmaxf(av.w, 0.f);
        }
        acc += av.x * W[(k + 0) * 256 + col] + av.y * W[(k + 1) * 256 + col] +
               av.z * W[(k + 2) * 256 + col] + av.w * W[(k + 3) * 256 + col];
    }
    C[col] = acc;
}
__global__ void sms_kernel(const float* __restrict__ S0, const float* __restrict__ S2,
                           const float* __restrict__ Wr0, const float* __restrict__ Wr2,
                           float* __restrict__ Bf) {
    int b = blockIdx.x;
    int w = threadIdx.x >> 5, lane = threadIdx.x & 31;
    int col = w * 32 + lane;
    const float* a;
    const float* W;
    float* C;
    if (b < DNA) { a = S0 + (size_t)b * 256; W = Wr0; C = Bf + (size_t)(DNF + b) * 256; }
    else {
        int rc = b - DNA;
        a = S2 + (size_t)rc * 256; W = Wr2; C = Bf + (size_t)(DNF + DNA + rc) * 256;
    }
    float acc = 0.0f;
#pragma unroll 4
    for (int k = 0; k < 256; k += 4) {
        float4 av = *(const float4*)(a + k);
        acc += av.x * W[(k + 0) * 256 + col] + av.y * W[(k + 1) * 256 + col] +
               av.z * W[(k + 2) * 256 + col] + av.w * W[(k + 3) * 256 + col];
    }
    C[col] += acc;
}

// ---------------- fused CSR gather (rel0 + rel2) ----------------
__global__ void gather_both_kernel(const float* __restrict__ tab,
                                   const int* __restrict__ csr0, const int* __restrict__ off0,
                                   const int* __restrict__ deg0, float* __restrict__ S0,
                                   const int* __restrict__ csr2, const int* __restrict__ off2,
                                   const int* __restrict__ deg2, float* __restrict__ S2) {
    int w = (blockIdx.x * blockDim.x + threadIdx.x) >> 5;
    int lane = threadIdx.x & 31;
    const int N0 = DNA * 8 * 8;
    const int N2 = DNC * 8 * 64;
    if (w >= N0 + N2) return;
    const int* csr;
    const int* offs;
    const int* deg;
    float* S;
    int row, cg, chunk, split;
    if (w < N0) {
        split = 8;
        row = w / 64; int rr = w % 64; cg = rr & 7; chunk = rr >> 3;
        csr = csr0; offs = off0; deg = deg0; S = S0;
    } else {
        int w2 = w - N0;
        split = 64;
        row = w2 / 512; int rr = w2 % 512; cg = rr & 7; chunk = rr >> 3;
        csr = csr2; offs = off2; deg = deg2; S = S2;
    }
    int col = cg * 32 + lane;
    int d = deg[row], beg = offs[row];
    int per = (d + split - 1) / split;
    int s0 = beg + chunk * per;
    int s1 = min(beg + d, s0 + per);
    if (s0 >= s1) return;
    float acc = 0.0f;
    int e = s0;
    for (; e + 4 <= s1; e += 4) {
        int i0 = csr[e], i1 = csr[e + 1], i2 = csr[e + 2], i3 = csr[e + 3];
        acc += (tab[(size_t)i0 * DD + col] + tab[(size_t)i1 * DD + col]) +
               (tab[(size_t)i2 * DD + col] + tab[(size_t)i3 * DD + col]);
    }
    for (; e < s1; e++) acc += tab[(size_t)csr[e] * DD + col];
    acc *= 1.0f / (float)max(d, 1);
    atomicAdd(&S[(size_t)row * DD + col], acc);
}

// ---------------- resident-smem bf16 split GEMM (u64 frags + 2-stage pipeline) ----------------
__device__ __forceinline__ uint32_t pack_bf16_hi(float f0, float f1) {
    return (uint32_t)__bfloat16_as_ushort(__float2bfloat16(f0)) |
           ((uint32_t)__bfloat16_as_ushort(__float2bfloat16(f1)) << 16);
}
__device__ __forceinline__ uint32_t pack_bf16_lo(float f0, float f1) {
    __nv_bfloat16 h0 = __float2bfloat16(f0);
    __nv_bfloat16 h1 = __float2bfloat16(f1);
    __nv_bfloat16 l0 = __float2bfloat16(f0 - __bfloat162float(h0));
    __nv_bfloat16 l1 = __float2bfloat16(f1 - __bfloat162float(h1));
    return (uint32_t)__bfloat16_as_ushort(l0) |
           ((uint32_t)__bfloat16_as_ushort(l1) << 16);
}
__device__ __forceinline__ void mma16816(float* c, const uint32_t* a,
                                         const uint32_t* b) {
    asm volatile(
        "mma.sync.aligned.m16n8k16.row.col.f32.bf16.bf16.f32 "
        "{%0,%1,%2,%3}, {%4,%5,%6,%7}, {%8,%9}, {%0,%1,%2,%3};"
        : "+f"(c[0]), "+f"(c[1]), "+f"(c[2]), "+f"(c[3])
        : "r"(a[0]), "r"(a[1]), "r"(a[2]), "r"(a[3]), "r"(b[0]), "r"(b[1]));
}
// slot permutation: pair p (0..15) -> slot; thread t reads slots {2t, 2t+1} =
// pairs {t, t+4} of its ks-half as one aligned u64.
__device__ __forceinline__ int pos16(int p) {
    return ((p >> 3) << 3) + ((p & 3) << 1) + ((p >> 2) & 1);
}

#define SPAD 18
#define CHUNK (128 * SPAD)
#define MM_DSMEM (3 * 8 * CHUNK * 4)

__global__ void __launch_bounds__(256)
mma_resident_kernel(const float* __restrict__ A,
                    const uint32_t* __restrict__ WhU,
                    const uint32_t* __restrict__ WlU,
                    const float* __restrict__ bias, float* __restrict__ C,
                    int M, int reluA) {
    extern __shared__ uint32_t dsm[];
    uint32_t* sAh = dsm;
    uint32_t* sAl = dsm + 8 * CHUNK;
    uint32_t* sB  = dsm + 16 * CHUNK;

    int tid = threadIdx.x;
    int lane = tid & 31, wid = tid >> 5;
    int warpM = wid >> 2;
    int warpN = wid & 3;
    int m0 = blockIdx.x * 128;
    int n0 = blockIdx.y * 128;

    float acc[4][4][4];
#pragma unroll
    for (int i = 0; i < 4; i++)
#pragma unroll
        for (int j = 0; j < 4; j++)
#pragma unroll
            for (int q = 0; q < 4; q++) acc[i][j][q] = 0.0f;

    // ---- load + split-convert A (once), chunk-major, pair-permuted slots ----
#pragma unroll 2
    for (int c = 0; c < 8; c++) {
#pragma unroll
        for (int j = 0; j < 4; j++) {
            int id = j * 256 + tid;
            int row = id >> 3, q = id & 7;
            int rg = m0 + row;
            float4 v = make_float4(0.f, 0.f, 0.f, 0.f);
            if (rg < M) v = *(const float4*)(A + (size_t)rg * 256 + c * 32 + q * 4);
            if (reluA) {
                v.x = fmaxf(v.x, 0.f); v.y = fmaxf(v.y, 0.f);
                v.z = fmaxf(v.z, 0.f); v.w = fmaxf(v.w, 0.f);
            }
            int rbse = c * CHUNK + row * SPAD;
            int s0 = rbse + pos16(2 * q);
            int s1 = rbse + pos16(2 * q + 1);
            sAh[s0] = pack_bf16_hi(v.x, v.y);
            sAh[s1] = pack_bf16_hi(v.z, v.w);
            sAl[s0] = pack_bf16_lo(v.x, v.y);
            sAl[s1] = pack_bf16_lo(v.z, v.w);
        }
    }
    // ---- load Bh (pair-permuted slots) ----
#pragma unroll 2
    for (int c = 0; c < 8; c++) {
#pragma unroll
        for (int j = 0; j < 8; j++) {
            int id = j * 256 + tid;
            int n = id >> 4, cc = id & 15;
            sB[c * CHUNK + n * SPAD + pos16(cc)] = WhU[(size_t)(n0 + n) * 128 + c * 16 + cc];
        }
    }
    __syncthreads();

    int rbase = warpM * 64 + (lane >> 2);
    int nbase = warpN * 32 + (lane >> 2);
    int tq = lane & 3;

    // fragment load for flattened step s (c = s>>1, ks = s&1)
    auto ldStep = [&](const uint32_t* aB, int s, uint32_t* af, uint32_t* bfr) {
        int c = s >> 1, ks = s & 1;
        const uint32_t* ac = aB + c * CHUNK;
        const uint32_t* bc = sB + c * CHUNK;
        int so = ks * 8 + tq * 2;
#pragma unroll
        for (int mt = 0; mt < 4; mt++) {
            int r = rbase + mt * 16;
            unsigned long long lo = *(const unsigned long long*)(ac + r * SPAD + so);
            unsigned long long hi = *(const unsigned long long*)(ac + (r + 8) * SPAD + so);
            af[mt * 4 + 0] = (uint32_t)lo; af[mt * 4 + 2] = (uint32_t)(lo >> 32);
            af[mt * 4 + 1] = (uint32_t)hi; af[mt * 4 + 3] = (uint32_t)(hi >> 32);
        }
#pragma unroll
        for (int nt = 0; nt < 4; nt++) {
            int n = nbase + nt * 8;
            unsigned long long v = *(const unsigned long long*)(bc + n * SPAD + so);
            bfr[nt * 2 + 0] = (uint32_t)v; bfr[nt * 2 + 1] = (uint32_t)(v >> 32);
        }
    };
    auto mmaStep = [&](const uint32_t* af, const uint32_t* bfr) {
#pragma unroll
        for (int mt = 0; mt < 4; mt++)
#pragma unroll
            for (int nt = 0; nt < 4; nt++)
                mma16816(acc[mt][nt], af + mt * 4, bfr + nt * 2);
    };
    // 2-stage software pipeline over the 16 (c,ks) steps
    auto mmaAll = [&](const uint32_t* aB) {
        uint32_t af0[16], bf0[8], af1[16], bf1[8];
        ldStep(aB, 0, af0, bf0);
#pragma unroll
        for (int s = 0; s < 16; s += 2) {
            ldStep(aB, s + 1, af1, bf1);
            mmaStep(af0, bf0);
            if (s + 2 < 16) ldStep(aB, s + 2, af0, bf0);
            mmaStep(af1, bf1);
        }
    };

    mmaAll(sAh);    // Ah @ Wh
    mmaAll(sAl);    // Al @ Wh
    __syncthreads();

    // ---- overwrite B with Bl ----
#pragma unroll 2
    for (int c = 0; c < 8; c++) {
#pragma unroll
        for (int j = 0; j < 8; j++) {
            int id = j * 256 + tid;
            int n = id >> 4, cc = id & 15;
            sB[c * CHUNK + n * SPAD + pos16(cc)] = WlU[(size_t)(n0 + n) * 128 + c * 16 + cc];
        }
    }
    __syncthreads();

    mmaAll(sAh);    // Ah @ Wl

    // ---- epilogue ----
#pragma unroll
    for (int mt = 0; mt < 4; mt++) {
        int r = m0 + warpM * 64 + mt * 16 + (lane >> 2);
#pragma unroll
        for (int nt = 0; nt < 4; nt++) {
            int c = n0 + warpN * 32 + nt * 8 + (lane & 3) * 2;
            float b0 = bias[c], b1 = bias[c + 1];
            if (r < M) {
                float2 v0 = make_float2(acc[mt][nt][0] + b0, acc[mt][nt][1] + b1);
                *(float2*)(C + (size_t)r * 256 + c) = v0;
            }
            if (r + 8 < M) {
                float2 v1 = make_float2(acc[mt][nt][2] + b0, acc[mt][nt][3] + b1);
                *(float2*)(C + (size_t)(r + 8) * 256 + c) = v1;
            }
        }
    }
}

// ---------------- fused scatter (rel1 + rel3) ----------------
__device__ __forceinline__ void red_add_v4(float* addr, float4 v) {
    asm volatile("red.global.add.v4.f32 [%0], {%1,%2,%3,%4};"
                 :: "l"(addr), "f"(v.x), "f"(v.y), "f"(v.z), "f"(v.w) : "memory");
}
__global__ void scatter_both_kernel(const float* __restrict__ Y1,
                                    const int* __restrict__ src1, const int* __restrict__ dst1,
                                    const float* __restrict__ inv1,
                                    const float* __restrict__ Y3,
                                    const int* __restrict__ src3, const int* __restrict__ dst3,
                                    const float* __restrict__ inv3,
                                    float* __restrict__ out) {
    int w = (blockIdx.x * blockDim.x + threadIdx.x) >> 5;
    int lane = threadIdx.x & 31;
    if (w >= 2 * DE) return;
    const float* tab;
    int s, d;
    float sc;
    if (w < DE) {
        s = src1[w]; d = dst1[w]; sc = inv1[d]; tab = Y1;
    } else {
        int e = w - DE;
        s = src3[e]; d = dst3[e]; sc = inv3[d]; tab = Y3;
    }
    const float4* in4 = (const float4*)(tab + (size_t)s * DD);
    float4 a = in4[lane], b = in4[lane + 32];
    a.x *= sc; a.y *= sc; a.z *= sc; a.w *= sc;
    b.x *= sc; b.y *= sc; b.z *= sc; b.w *= sc;
    float* ob = out + (size_t)d * DD;
    red_add_v4(ob + lane * 4, a);
    red_add_v4(ob + (lane + 32) * 4, b);
}

// readout
__global__ void readout_kernel(const float* __restrict__ X, const float* __restrict__ Wout,
                               const float* __restrict__ bout, float* __restrict__ out,
                               int M) {
    int w = (blockIdx.x * blockDim.x + threadIdx.x) >> 5;
    int lane = threadIdx.x & 31;
    if (w >= M) return;
    const float4* x4 = (const float4*)(X + (size_t)w * DD);
    const float4* w4 = (const float4*)Wout;
    float4 a = x4[lane], wa = w4[lane];
    float4 b = x4[lane + 32], wb = w4[lane + 32];
    float s = fmaxf(a.x, 0.f) * wa.x + fmaxf(a.y, 0.f) * wa.y +
              fmaxf(a.z, 0.f) * wa.z + fmaxf(a.w, 0.f) * wa.w +
              fmaxf(b.x, 0.f) * wb.x + fmaxf(b.y, 0.f) * wb.y +
              fmaxf(b.z, 0.f) * wb.z + fmaxf(b.w, 0.f) * wb.w;
#pragma unroll
    for (int off = 16; off > 0; off >>= 1) s += __shfl_down_sync(0xffffffffu, s, off);
    if (lane == 0) out[w] = s + bout[0];
}

// ---------------- launch ----------------
extern "C" void kernel_launch(void* const* d_in, const int* in_sizes, int n_in,
                              void* d_out, int out_size) {
    (void)in_sizes; (void)n_in; (void)out_size;
    const float* x_flight  = (const float*)d_in[0];
    const float* x_airport = (const float*)d_in[1];
    const float* x_carrier = (const float*)d_in[2];
    const float* W_f = (const float*)d_in[3];
    const float* b_f = (const float*)d_in[4];
    const float* W_a = (const float*)d_in[5];
    const float* b_a = (const float*)d_in[6];
    const float* W_c = (const float*)d_in[7];
    const float* b_c = (const float*)d_in[8];
    const float* basis0 = (const float*)d_in[9];
    const float* comp0  = (const float*)d_in[10];
    const float* root0  = (const float*)d_in[11];
    const float* bias0  = (const float*)d_in[12];
    const float* basis1 = (const float*)d_in[13];
    const float* comp1  = (const float*)d_in[14];
    const float* root1  = (const float*)d_in[15];
    const float* bias1  = (const float*)d_in[16];
    const float* W_out  = (const float*)d_in[17];
    const float* b_out  = (const float*)d_in[18];
    const int* src0 = (const int*)d_in[19];
    const int* dst0 = (const int*)d_in[20];
    const int* src1 = (const int*)d_in[21];
    const int* dst1 = (const int*)d_in[22];
    const int* src2 = (const int*)d_in[23];
    const int* dst2 = (const int*)d_in[24];
    const int* src3 = (const int*)d_in[25];
    const int* dst3 = (const int*)d_in[26];
    float* out_final = (float*)d_out;

    void *pA, *pB, *pW, *pWs, *pY1, *pY3, *pS0, *pS2;
    void *pd0, *pd1, *pd2, *pd3, *pi1, *pi3;
    void *po0, *pc0, *po2, *pc2, *pe0, *pe2;
    cudaGetSymbolAddress(&pA, g_A);       cudaGetSymbolAddress(&pB, g_Bf);
    cudaGetSymbolAddress(&pW, g_W);       cudaGetSymbolAddress(&pWs, g_Wsplit);
    cudaGetSymbolAddress(&pY1, g_Y1);     cudaGetSymbolAddress(&pY3, g_Y3);
    cudaGetSymbolAddress(&pS0, g_S0);     cudaGetSymbolAddress(&pS2, g_S2);
    cudaGetSymbolAddress(&pd0, g_deg0);   cudaGetSymbolAddress(&pd1, g_deg1);
    cudaGetSymbolAddress(&pd2, g_deg2);   cudaGetSymbolAddress(&pd3, g_deg3);
    cudaGetSymbolAddress(&pi1, g_inv1);   cudaGetSymbolAddress(&pi3, g_inv3);
    cudaGetSymbolAddress(&po0, g_off0);   cudaGetSymbolAddress(&pc0, g_cur0);
    cudaGetSymbolAddress(&po2, g_off2);   cudaGetSymbolAddress(&pc2, g_cur2);
    cudaGetSymbolAddress(&pe0, g_csr0);   cudaGetSymbolAddress(&pe2, g_csr2);

    float* A = (float*)pA;  float* Bf = (float*)pB;  float* W = (float*)pW;
    __nv_bfloat16* Ws = (__nv_bfloat16*)pWs;
    float* Y1 = (float*)pY1; float* Y3 = (float*)pY3;
    float* S0 = (float*)pS0; float* S2 = (float*)pS2;
    int* deg0 = (int*)pd0; int* deg1 = (int*)pd1;
    int* deg2 = (int*)pd2; int* deg3 = (int*)pd3;
    float* inv1 = (float*)pi1; float* inv3 = (float*)pi3;
    int* off0 = (int*)po0; int* cur0 = (int*)pc0;
    int* off2 = (int*)po2; int* cur2 = (int*)pc2;
    int* csr0 = (int*)pe0; int* csr2 = (int*)pe2;

    const size_t WSZ = (size_t)DD * DD;
    float* W0 = W;
    float* W1 = W + DR * WSZ;
    __nv_bfloat16* Wh0 = Ws;
    __nv_bfloat16* Wl0 = Ws + WSZ;
    __nv_bfloat16* Wh1 = Ws + 2 * WSZ;
    __nv_bfloat16* Wl1 = Ws + 3 * WSZ;

    cudaFuncSetAttribute(mma_resident_kernel,
                         cudaFuncAttributeMaxDynamicSharedMemorySize, MM_DSMEM);

    dim3 gFull((DNT + 127) / 128, 2);
    dim3 gNF((DNF + 127) / 128, 2);
    const int scatter2Blocks = (2 * DE * 32 + 255) / 256;
    const int gatherBlocks = ((DNA * 64 + DNC * 512) * 32 + 255) / 256;

    // 0: deg zero
    zero_deg_all2_kernel<<<784, 256>>>(deg1, deg3, deg0, deg2);
    // 1: split root0
    prep_wsplit_kernel<<<(DD * DD + 255) / 256, 256>>>(root0, Wh0, Wl0);
    // 2: all encoders fused -> A
    encode_all_kernel<<<ENC_FBLOCKS + DNA + DNC, 256>>>(
        x_flight, W_f, b_f, x_airport, W_a, b_a, x_carrier, W_c, b_c, A);
    // 3: layer-0 root GEMM (ncu capture target)
    mma_resident_kernel<<<gFull, 256, MM_DSMEM>>>(
        A, (const uint32_t*)Wh0, (const uint32_t*)Wl0, bias0, Bf, DNT, 0);
    // 4-5: degree counts
    count_flight_kernel<<<1954, 256>>>(dst1, deg1, dst3, deg3);
    count_small_kernel<<<296, 256>>>(dst0, deg0, dst2, deg2);
    // 6: split root1
    prep_wsplit_kernel<<<(DD * DD + 255) / 256, 256>>>(root1, Wh1, Wl1);
    // 7: relation weights both layers
    compute_W_all_kernel<<<2048, 256>>>(basis0, comp0, W0, basis1, comp1, W1);
    // 8-10: inv, scans, CSR fill
    make_inv_all_kernel<<<782, 256>>>(deg1, inv1, deg3, inv3);
    scan_small_kernel<<<2, 512>>>(deg0, off0, cur0, deg2, off2, cur2);
    fill_csr_both_kernel<<<1954, 256>>>(src0, dst0, cur0, csr0, src2, dst2, cur2, csr2);
    // 11: layer-0 relation messages
    yms_kernel<<<DNA + DNC, 256>>>(A + (size_t)DNF * DD, A + (size_t)(DNF + DNA) * DD,
                                   W0 + 1 * WSZ, W0 + 3 * WSZ, Y1, Y3, 0);
    // 12-14: rel0/rel2 aggregates
    zero_S_kernel<<<430, 256>>>(S0, S2);
    gather_both_kernel<<<gatherBlocks, 256>>>(A, csr0, off0, deg0, S0,
                                              csr2, off2, deg2, S2);
    sms_kernel<<<DNA + DNC, 256>>>(S0, S2, W0 + 0 * WSZ, W0 + 2 * WSZ, Bf);
    // 15: fused scatter layer 0
    scatter_both_kernel<<<scatter2Blocks, 256>>>(Y1, src1, dst1, inv1,
                                                 Y3, src3, dst3, inv3, Bf);
    // 16: layer-1 root GEMM
    mma_resident_kernel<<<gNF, 256, MM_DSMEM>>>(
        Bf, (const uint32_t*)Wh1, (const uint32_t*)Wl1, bias1, A, DNF, 1);
    // 17: layer-1 relation messages
    yms_kernel<<<DNA + DNC, 256>>>(Bf + (size_t)DNF * DD, Bf + (size_t)(DNF + DNA) * DD,
                                   W1 + 1 * WSZ, W1 + 3 * WSZ, Y1, Y3, 1);
    // 18: fused scatter layer 1
    scatter_both_kernel<<<scatter2Blocks, 256>>>(Y1, src1, dst1, inv1,
                                                 Y3, src3, dst3, inv3, A);
    // 19: readout
    readout_kernel<<<(DNF * 32 + 255) / 256, 256>>>(A, W_out, b_out, out_final, DNF);
}